// round 7
// baseline (speedup 1.0000x reference)
#include <cuda_runtime.h>

// Problem constants (reference: N=50000, M=8192, C=768, NUM_BATCH=4, GRID=128)
#define NPTS_MAX 50000
#define MTGT_MAX 8192
#define CCH      768
#define NB       4

#define CSHIFT   3                    // cell edge = 8
#define GC       16                   // cells per axis (128 >> 3)
#define NCELLS   (NB * GC * GC * GC)  // 16384
#define CAP      32                   // points per cell (lambda~3)
#define TPBF     256                  // threads per block (fused kernel)

// ------- device scratch (static; no allocation anywhere) -------
// g_count/g_ovn are zero at module load; reset in phase C for the next call.
__device__ int      g_count[NCELLS];
__device__ int2     g_cells[NCELLS * CAP];    // (packed_xyz, orig_idx)
__device__ int      g_ovn;
__device__ int4     g_ovf[NPTS_MAX];          // overflow: (packed, idx, batch, 0)
__device__ unsigned g_best[MTGT_MAX];         // (d2<<16)|idx; rewritten every call

// software grid barrier state (gen monotonically increases across replays)
__device__ unsigned          g_barcnt = 0;
__device__ volatile unsigned g_bargen = 0;

__device__ __forceinline__ void gridbar(int nblocks) {
    __syncthreads();
    if (threadIdx.x == 0) {
        unsigned gen = g_bargen;
        __threadfence();                       // publish this block's phase writes
        if (atomicAdd(&g_barcnt, 1u) == (unsigned)nblocks - 1u) {
            g_barcnt = 0;
            __threadfence();
            g_bargen = gen + 1u;               // release all spinners
        } else {
            while (g_bargen == gen) __nanosleep(40);
        }
        __threadfence();                       // order subsequent reads
    }
    __syncthreads();
}

// candidate evaluation: packed key = d2*65536 + idx (d2<2^16, idx<2^16)
__device__ __forceinline__ void eval(unsigned tp, int2 q, unsigned& best) {
    unsigned ad = __vabsdiffu4(tp, (unsigned)q.x);    // |dx|,|dy|,|dz|,0 per byte
    best = min(best, __dp4a(ad, ad, 0u) * 65536u + (unsigned)q.y);
}

// ------- single persistent kernel: build -> barrier -> search -> barrier ->
// ------- reset + gather. grid MUST be <= #SMs (1 block/SM co-residency). ----
__global__ void __launch_bounds__(TPBF) k_fused(
    const int4* __restrict__ coords, int n,
    const int4* __restrict__ tc, int m,
    const float* __restrict__ feat, float* __restrict__ out)
{
    const int nbk = gridDim.x;
    const int tid = blockIdx.x * TPBF + threadIdx.x;
    const int nth = nbk * TPBF;

    // ---- Phase A: bin source points (g_count is zero on entry) ----
    for (int i = tid; i < n; i += nth) {
        int4 r = coords[i];                           // (batch,x,y,z) LDG.128
        int b = r.x & (NB - 1);
        int cell = ((b * GC + (r.w >> CSHIFT)) * GC + (r.z >> CSHIFT)) * GC
                 + (r.y >> CSHIFT);
        int packed = r.y | (r.z << 8) | (r.w << 16);
        int pos = atomicAdd(&g_count[cell], 1);
        if (pos < CAP) g_cells[cell * CAP + pos] = make_int2(packed, i);
        else {                                        // never in practice; airtight
            int op = atomicAdd(&g_ovn, 1);
            g_ovf[op] = make_int4(packed, i, b, 0);
        }
    }
    gridbar(nbk);

    // ---- Phase B: per-target NN search with shell termination ----
    // j mapping spreads targets evenly across SMs (~2 warps/SM active).
    for (int j = threadIdx.x * nbk + blockIdx.x; j < m; j += nth) {
        int4 r = tc[j];
        int b = r.x & (NB - 1);
        unsigned tp = (unsigned)(r.y | (r.z << 8) | (r.w << 16));
        int cx = r.y >> CSHIFT, cy = r.z >> CSHIFT, cz = r.w >> CSHIFT;
        unsigned best = 0xFFFFFFFFu;

        int ovn = g_ovn;                              // normally 0
        for (int o = 0; o < ovn; o++) {
            int4 v = g_ovf[o];
            if (v.z == b) eval(tp, make_int2(v.x, v.y), best);
        }

        // k=1 fast path: 27 cells fully unrolled -> high MLP on count loads
        #pragma unroll
        for (int dz = -1; dz <= 1; dz++)
        #pragma unroll
        for (int dy = -1; dy <= 1; dy++)
        #pragma unroll
        for (int dx = -1; dx <= 1; dx++) {
            int x = cx + dx, y = cy + dy, z = cz + dz;
            if ((unsigned)x < GC && (unsigned)y < GC && (unsigned)z < GC) {
                int cell = ((b * GC + z) * GC + y) * GC + x;
                int cnt = min(g_count[cell], CAP);
                const int2* p = &g_cells[cell * CAP];
                for (int q = 0; q < cnt; q++) eval(tp, p[q], best);
            }
        }

        // expand shells only if nearest could lie outside radius-1 (rare).
        // After radius k, any unexamined point has d2 >= (8k)^2; stop only on
        // STRICT best_d2 < 64k^2 so equal-distance outside ties (smaller idx)
        // are still examined -> exact argmin first-index semantics.
        if ((best >> 16) >= 64u) {
            for (int k = 2; k <= GC; k++) {
                int x0 = max(cx - k, 0), x1 = min(cx + k, GC - 1);
                int y0 = max(cy - k, 0), y1 = min(cy + k, GC - 1);
                int z0 = max(cz - k, 0), z1 = min(cz + k, GC - 1);
                for (int z = z0; z <= z1; z++)
                for (int y = y0; y <= y1; y++)
                for (int x = x0; x <= x1; x++) {      // redo-all: min-safe dups
                    int cell = ((b * GC + z) * GC + y) * GC + x;
                    int cnt = min(g_count[cell], CAP);
                    const int2* p = &g_cells[cell * CAP];
                    for (int q = 0; q < cnt; q++) eval(tp, p[q], best);
                }
                if ((best >> 16) < (unsigned)(64 * k * k)) break;
                if (x0 == 0 && x1 == GC - 1 && y0 == 0 && y1 == GC - 1 &&
                    z0 == 0 && z1 == GC - 1) break;
            }
        }
        g_best[j] = best;
    }
    gridbar(nbk);

    // ---- Phase C: reset bin state for next replay + gather rows ----
    for (int i = tid; i < NCELLS; i += nth) g_count[i] = 0;
    if (tid == 0) g_ovn = 0;

    const int chunks = m * (CCH / 16);                // 64B chunks, 48 per row
    for (int cid = tid; cid < chunks; cid += nth) {
        int row = cid / (CCH / 16);
        int sub = cid - row * (CCH / 16);
        unsigned k = g_best[row];
        float4* o = (float4*)(out + (size_t)row * CCH) + sub * 4;
        if (k == 0xFFFFFFFFu) {                       // empty batch -> zeros
            float4 zz = make_float4(0.f, 0.f, 0.f, 0.f);
            o[0] = zz; o[1] = zz; o[2] = zz; o[3] = zz;
        } else {
            const float4* f =
                (const float4*)(feat + (size_t)(k & 0xFFFFu) * CCH) + sub * 4;
            float4 v0 = f[0], v1 = f[1], v2 = f[2], v3 = f[3];
            o[0] = v0; o[1] = v1; o[2] = v2; o[3] = v3;
        }
    }
}

extern "C" void kernel_launch(void* const* d_in, const int* in_sizes, int n_in,
                              void* d_out, int out_size) {
    const float* feat    = (const float*)d_in[0];
    const int4*  coords  = (const int4*)d_in[1];
    const int4*  tcoords = (const int4*)d_in[2];
    float*       out     = (float*)d_out;

    int n = in_sizes[1] / 4;   // 50000
    int m = in_sizes[2] / 4;   // 8192

    int sms = 0;
    cudaDeviceGetAttribute(&sms, cudaDevAttrMultiProcessorCount, 0);
    if (sms < 1) sms = 1;      // defensive; 1 block/SM -> co-resident barrier

    k_fused<<<sms, TPBF>>>(coords, n, tcoords, m, feat, out);
}

// round 8
// speedup vs baseline: 1.0397x; 1.0397x over previous
#include <cuda_runtime.h>

// Problem constants (reference: N=50000, M=8192, C=768, NUM_BATCH=4, GRID=128)
#define NPTS_MAX 50000
#define MTGT_MAX 8192
#define CCH      768
#define NB       4

#define TPB   256     // search threads per block, 1 target per thread (R3 layout)
#define TILE  2048    // smem candidate tile (int2 = 16KB)
#define SEGS  16      // candidate-dimension segments per batch

// ------- device scratch (static; no allocation anywhere) -------
// Fixed-capacity per-batch regions: batch b owns [b*CAP, b*CAP + count_b)
__device__ int2     g_cbucket[NB * NPTS_MAX];  // (packed_xyz, orig_idx)
__device__ int2     g_tbucket[NB * MTGT_MAX];  // (packed_xyz, orig_idx)
__device__ unsigned g_best[MTGT_MAX];          // (d2<<16)|src_idx, 0xFFFFFFFF=none
__device__ int      g_ccur[NB], g_tcur[NB];    // cursors: zeroed at END of gather
                                               // (module-load zeros cover call #1)

// ------- kernel 1: fused scatter (+ g_best init for this replay) -------
__global__ void k_scatter_all(const int4* __restrict__ coords, int n,
                              const int4* __restrict__ tcoords, int m) {
    int i = blockIdx.x * blockDim.x + threadIdx.x;
    if (i < m) g_best[i] = 0xFFFFFFFFu;          // init before search launch
    if (i < n) {
        int4 r = coords[i];                       // (batch,x,y,z) one LDG.128
        int b = r.x & (NB - 1);
        unsigned mask = __match_any_sync(__activemask(), b);
        int lane = threadIdx.x & 31;
        int leader = __ffs(mask) - 1;
        int pos = 0;
        if (lane == leader) pos = atomicAdd(&g_ccur[b], __popc(mask));
        pos = __shfl_sync(mask, pos, leader);
        pos += __popc(mask & ((1u << lane) - 1u));
        int packed = r.y | (r.z << 8) | (r.w << 16);   // bytes: x,y,z,0
        g_cbucket[b * NPTS_MAX + pos] = make_int2(packed, i);
    } else if (i < n + m) {
        int j = i - n;
        int4 r = tcoords[j];
        int b = r.x & (NB - 1);
        unsigned mask = __match_any_sync(__activemask(), b);
        int lane = threadIdx.x & 31;
        int leader = __ffs(mask) - 1;
        int pos = 0;
        if (lane == leader) pos = atomicAdd(&g_tcur[b], __popc(mask));
        pos = __shfl_sync(mask, pos, leader);
        pos += __popc(mask & ((1u << lane) - 1u));
        int packed = r.y | (r.z << 8) | (r.w << 16);
        g_tbucket[b * MTGT_MAX + pos] = make_int2(packed, j);
    }
}

// ------- kernel 2: brute NN search. R3 layout (1 target/thread), but the ----
// ------- inner loop reads 2 candidates per LDS.128 (4.5 slots/candidate). ---
__global__ void __launch_bounds__(TPB) k_search() {
    int b = blockIdx.z;
    int tcount = g_tcur[b];
    int tstart = blockIdx.x * TPB;
    if (tstart >= tcount) return;
    int ccount = g_ccur[b];
    if (ccount <= 0) return;                 // empty batch -> best stays 0xFFFFFFFF
    int seg = (ccount + SEGS - 1) / SEGS;
    int cs = blockIdx.y * seg;
    int ce = min(cs + seg, ccount);
    if (cs >= ce) return;

    const int2* cb = g_cbucket + b * NPTS_MAX;
    __shared__ __align__(16) int2 sh[TILE];

    int ti = tstart + threadIdx.x;
    bool active = ti < tcount;
    int2 t = active ? g_tbucket[b * MTGT_MAX + ti] : make_int2(0, 0);
    unsigned tp = (unsigned)t.x;
    unsigned best = 0xFFFFFFFFu;

    int2 padv = cb[cs];                      // real candidate; duplicates min-safe

    for (int c = cs; c < ce; c += TILE) {
        int nn = min(TILE, ce - c);
        int npad = (nn + 15) & ~15;          // multiple of 16 cands = 8 int4
        for (int j = threadIdx.x; j < nn; j += TPB) sh[j] = cb[c + j];
        for (int j = nn + threadIdx.x; j < npad; j += TPB) sh[j] = padv;
        __syncthreads();
        const int4* sh4 = (const int4*)sh;
        int n4 = npad >> 1;
        #pragma unroll 8
        for (int j = 0; j < n4; j++) {
            int4 q = sh4[j];                 // two (packed,idx) candidates
            unsigned ad;
            ad = __vabsdiffu4(tp, (unsigned)q.x);
            best = min(best, __dp4a(ad, ad, 0u) * 65536u + (unsigned)q.y);
            ad = __vabsdiffu4(tp, (unsigned)q.z);
            best = min(best, __dp4a(ad, ad, 0u) * 65536u + (unsigned)q.w);
        }
        __syncthreads();
    }
    if (active) atomicMin(&g_best[t.y], best);
}

// ------- kernel 3: gather rows (64B chunk/thread, MLP=4) + cursor reset -----
__global__ void k_gather(const float* __restrict__ feat, float* __restrict__ out,
                         int m) {
    int cid = blockIdx.x * blockDim.x + threadIdx.x;     // 64B chunk id
    int total = m * (CCH / 16);                          // 48 chunks per row
    if (cid < total) {
        int row = cid / (CCH / 16);
        int sub = cid - row * (CCH / 16);
        unsigned k = g_best[row];
        float4* o = (float4*)(out + (size_t)row * CCH) + sub * 4;
        if (k == 0xFFFFFFFFu) {                          // empty batch -> zeros
            float4 z = make_float4(0.f, 0.f, 0.f, 0.f);
            o[0] = z; o[1] = z; o[2] = z; o[3] = z;
        } else {
            const float4* f =
                (const float4*)(feat + (size_t)(k & 0xFFFFu) * CCH) + sub * 4;
            float4 v0 = f[0], v1 = f[1], v2 = f[2], v3 = f[3];
            o[0] = v0; o[1] = v1; o[2] = v2; o[3] = v3;
        }
    }
    // reset cursors for the NEXT replay (cursors unused by this kernel: no race)
    if (blockIdx.x == 0 && threadIdx.x < NB) {
        g_ccur[threadIdx.x] = 0;
        g_tcur[threadIdx.x] = 0;
    }
}

extern "C" void kernel_launch(void* const* d_in, const int* in_sizes, int n_in,
                              void* d_out, int out_size) {
    const float* feat    = (const float*)d_in[0];
    const int4*  coords  = (const int4*)d_in[1];
    const int4*  tcoords = (const int4*)d_in[2];
    float*       out     = (float*)d_out;

    int n = in_sizes[1] / 4;   // 50000
    int m = in_sizes[2] / 4;   // 8192

    k_scatter_all<<<(n + m + 255) / 256, 256>>>(coords, n, tcoords, m);

    int tiles = (m + TPB - 1) / TPB;           // worst case: all in one batch
    dim3 sgrid(tiles, SEGS, NB);
    k_search<<<sgrid, TPB>>>();

    int chunks = m * (CCH / 16);
    k_gather<<<(chunks + 255) / 256, 256>>>(feat, out, m);
}

// round 9
// speedup vs baseline: 1.0403x; 1.0006x over previous
#include <cuda_runtime.h>

// Problem constants (reference: N=50000, M=8192, C=768, NUM_BATCH=4, GRID=128)
#define NPTS_MAX 50000
#define MTGT_MAX 8192
#define CCH      768
#define NB       4

#define TPB   256     // search threads per block, 1 target per thread (R3 layout)
#define TILE  2048    // smem candidate tile (int2 = 16KB)
#define SEGS  16      // candidate-dimension segments per batch

// ------- device scratch (static; no allocation anywhere) -------
// Fixed-capacity per-batch regions: batch b owns [b*CAP, b*CAP + count_b)
__device__ int2     g_cbucket[NB * NPTS_MAX];  // (packed_xyz, orig_idx)
__device__ int2     g_tbucket[NB * MTGT_MAX];  // (packed_xyz, orig_idx)
__device__ unsigned g_best[MTGT_MAX];          // (d2<<16)|src_idx, 0xFFFFFFFF=none
__device__ int      g_ccur[NB], g_tcur[NB];    // cursors: zeroed at END of gather
                                               // (module-load zeros cover call #1)

// ------- kernel 1: fused scatter (+ g_best init for this replay) -------
__global__ void k_scatter_all(const int4* __restrict__ coords, int n,
                              const int4* __restrict__ tcoords, int m) {
    int i = blockIdx.x * blockDim.x + threadIdx.x;
    if (i < m) g_best[i] = 0xFFFFFFFFu;          // init before search launch
    if (i < n) {
        int4 r = coords[i];                       // (batch,x,y,z) one LDG.128
        int b = r.x & (NB - 1);
        unsigned mask = __match_any_sync(__activemask(), b);
        int lane = threadIdx.x & 31;
        int leader = __ffs(mask) - 1;
        int pos = 0;
        if (lane == leader) pos = atomicAdd(&g_ccur[b], __popc(mask));
        pos = __shfl_sync(mask, pos, leader);
        pos += __popc(mask & ((1u << lane) - 1u));
        int packed = r.y | (r.z << 8) | (r.w << 16);   // bytes: x,y,z,0
        g_cbucket[b * NPTS_MAX + pos] = make_int2(packed, i);
    } else if (i < n + m) {
        int j = i - n;
        int4 r = tcoords[j];
        int b = r.x & (NB - 1);
        unsigned mask = __match_any_sync(__activemask(), b);
        int lane = threadIdx.x & 31;
        int leader = __ffs(mask) - 1;
        int pos = 0;
        if (lane == leader) pos = atomicAdd(&g_tcur[b], __popc(mask));
        pos = __shfl_sync(mask, pos, leader);
        pos += __popc(mask & ((1u << lane) - 1u));
        int packed = r.y | (r.z << 8) | (r.w << 16);
        g_tbucket[b * MTGT_MAX + pos] = make_int2(packed, j);
    }
}

// ------- kernel 2: brute NN search. R3 layout (1 target/thread), but the ----
// ------- inner loop reads 2 candidates per LDS.128 (4.5 slots/candidate). ---
__global__ void __launch_bounds__(TPB) k_search() {
    int b = blockIdx.z;
    int tcount = g_tcur[b];
    int tstart = blockIdx.x * TPB;
    if (tstart >= tcount) return;
    int ccount = g_ccur[b];
    if (ccount <= 0) return;                 // empty batch -> best stays 0xFFFFFFFF
    int seg = (ccount + SEGS - 1) / SEGS;
    int cs = blockIdx.y * seg;
    int ce = min(cs + seg, ccount);
    if (cs >= ce) return;

    const int2* cb = g_cbucket + b * NPTS_MAX;
    __shared__ __align__(16) int2 sh[TILE];

    int ti = tstart + threadIdx.x;
    bool active = ti < tcount;
    int2 t = active ? g_tbucket[b * MTGT_MAX + ti] : make_int2(0, 0);
    unsigned tp = (unsigned)t.x;
    unsigned best = 0xFFFFFFFFu;

    int2 padv = cb[cs];                      // real candidate; duplicates min-safe

    for (int c = cs; c < ce; c += TILE) {
        int nn = min(TILE, ce - c);
        int npad = (nn + 15) & ~15;          // multiple of 16 cands = 8 int4
        for (int j = threadIdx.x; j < nn; j += TPB) sh[j] = cb[c + j];
        for (int j = nn + threadIdx.x; j < npad; j += TPB) sh[j] = padv;
        __syncthreads();
        const int4* sh4 = (const int4*)sh;
        int n4 = npad >> 1;
        #pragma unroll 8
        for (int j = 0; j < n4; j++) {
            int4 q = sh4[j];                 // two (packed,idx) candidates
            unsigned ad;
            ad = __vabsdiffu4(tp, (unsigned)q.x);
            best = min(best, __dp4a(ad, ad, 0u) * 65536u + (unsigned)q.y);
            ad = __vabsdiffu4(tp, (unsigned)q.z);
            best = min(best, __dp4a(ad, ad, 0u) * 65536u + (unsigned)q.w);
        }
        __syncthreads();
    }
    if (active) atomicMin(&g_best[t.y], best);
}

// ------- kernel 3: gather rows (64B chunk/thread, MLP=4) + cursor reset -----
__global__ void k_gather(const float* __restrict__ feat, float* __restrict__ out,
                         int m) {
    int cid = blockIdx.x * blockDim.x + threadIdx.x;     // 64B chunk id
    int total = m * (CCH / 16);                          // 48 chunks per row
    if (cid < total) {
        int row = cid / (CCH / 16);
        int sub = cid - row * (CCH / 16);
        unsigned k = g_best[row];
        float4* o = (float4*)(out + (size_t)row * CCH) + sub * 4;
        if (k == 0xFFFFFFFFu) {                          // empty batch -> zeros
            float4 z = make_float4(0.f, 0.f, 0.f, 0.f);
            o[0] = z; o[1] = z; o[2] = z; o[3] = z;
        } else {
            const float4* f =
                (const float4*)(feat + (size_t)(k & 0xFFFFu) * CCH) + sub * 4;
            float4 v0 = f[0], v1 = f[1], v2 = f[2], v3 = f[3];
            o[0] = v0; o[1] = v1; o[2] = v2; o[3] = v3;
        }
    }
    // reset cursors for the NEXT replay (cursors unused by this kernel: no race)
    if (blockIdx.x == 0 && threadIdx.x < NB) {
        g_ccur[threadIdx.x] = 0;
        g_tcur[threadIdx.x] = 0;
    }
}

extern "C" void kernel_launch(void* const* d_in, const int* in_sizes, int n_in,
                              void* d_out, int out_size) {
    const float* feat    = (const float*)d_in[0];
    const int4*  coords  = (const int4*)d_in[1];
    const int4*  tcoords = (const int4*)d_in[2];
    float*       out     = (float*)d_out;

    int n = in_sizes[1] / 4;   // 50000
    int m = in_sizes[2] / 4;   // 8192

    k_scatter_all<<<(n + m + 255) / 256, 256>>>(coords, n, tcoords, m);

    int tiles = (m + TPB - 1) / TPB;           // worst case: all in one batch
    dim3 sgrid(tiles, SEGS, NB);
    k_search<<<sgrid, TPB>>>();

    int chunks = m * (CCH / 16);
    k_gather<<<(chunks + 255) / 256, 256>>>(feat, out, m);
}

// round 12
// speedup vs baseline: 1.0601x; 1.0190x over previous
#include <cuda_runtime.h>

// Problem constants (reference: N=50000, M=8192, C=768, NUM_BATCH=4, GRID=128)
#define NPTS_MAX 50000
#define MTGT_MAX 8192
#define CCH      768
#define NB       4

#define TPB   256     // search threads per block, 1 target per thread (R3 layout)
#define TILE  2048    // smem candidate tile (int2 = 16KB)
#define SEGS  16      // candidate-dimension segments per batch

// ------- device scratch (static; no allocation anywhere) -------
// Fixed-capacity per-batch regions: batch b owns [b*CAP, b*CAP + count_b)
__device__ int2     g_cbucket[NB * NPTS_MAX];  // (packed_xyz, orig_idx)
__device__ int2     g_tbucket[NB * MTGT_MAX];  // (packed_xyz, orig_idx)
__device__ unsigned g_best[MTGT_MAX];          // (d2<<16)|src_idx, 0xFFFFFFFF=none
__device__ int      g_ccur[NB], g_tcur[NB];    // cursors: zeroed at END of gather
                                               // (module-load zeros cover call #1)

// ------- kernel 1: fused scatter (+ g_best init for this replay) -------
__global__ void k_scatter_all(const int4* __restrict__ coords, int n,
                              const int4* __restrict__ tcoords, int m) {
    int i = blockIdx.x * blockDim.x + threadIdx.x;
    if (i < m) g_best[i] = 0xFFFFFFFFu;          // init before search launch
    if (i < n) {
        int4 r = coords[i];                       // (batch,x,y,z) one LDG.128
        int b = r.x & (NB - 1);
        unsigned mask = __match_any_sync(__activemask(), b);
        int lane = threadIdx.x & 31;
        int leader = __ffs(mask) - 1;
        int pos = 0;
        if (lane == leader) pos = atomicAdd(&g_ccur[b], __popc(mask));
        pos = __shfl_sync(mask, pos, leader);
        pos += __popc(mask & ((1u << lane) - 1u));
        int packed = r.y | (r.z << 8) | (r.w << 16);   // bytes: x,y,z,0
        g_cbucket[b * NPTS_MAX + pos] = make_int2(packed, i);
    } else if (i < n + m) {
        int j = i - n;
        int4 r = tcoords[j];
        int b = r.x & (NB - 1);
        unsigned mask = __match_any_sync(__activemask(), b);
        int lane = threadIdx.x & 31;
        int leader = __ffs(mask) - 1;
        int pos = 0;
        if (lane == leader) pos = atomicAdd(&g_tcur[b], __popc(mask));
        pos = __shfl_sync(mask, pos, leader);
        pos += __popc(mask & ((1u << lane) - 1u));
        int packed = r.y | (r.z << 8) | (r.w << 16);
        g_tbucket[b * MTGT_MAX + pos] = make_int2(packed, j);
    }
}

// ------- kernel 2: brute NN search. R3 layout (1 target/thread), but the ----
// ------- inner loop reads 2 candidates per LDS.128 (4.5 slots/candidate). ---
__global__ void __launch_bounds__(TPB) k_search() {
    int b = blockIdx.z;
    int tcount = g_tcur[b];
    int tstart = blockIdx.x * TPB;
    if (tstart >= tcount) return;
    int ccount = g_ccur[b];
    if (ccount <= 0) return;                 // empty batch -> best stays 0xFFFFFFFF
    int seg = (ccount + SEGS - 1) / SEGS;
    int cs = blockIdx.y * seg;
    int ce = min(cs + seg, ccount);
    if (cs >= ce) return;

    const int2* cb = g_cbucket + b * NPTS_MAX;
    __shared__ __align__(16) int2 sh[TILE];

    int ti = tstart + threadIdx.x;
    bool active = ti < tcount;
    int2 t = active ? g_tbucket[b * MTGT_MAX + ti] : make_int2(0, 0);
    unsigned tp = (unsigned)t.x;
    unsigned best = 0xFFFFFFFFu;

    int2 padv = cb[cs];                      // real candidate; duplicates min-safe

    for (int c = cs; c < ce; c += TILE) {
        int nn = min(TILE, ce - c);
        int npad = (nn + 15) & ~15;          // multiple of 16 cands = 8 int4
        for (int j = threadIdx.x; j < nn; j += TPB) sh[j] = cb[c + j];
        for (int j = nn + threadIdx.x; j < npad; j += TPB) sh[j] = padv;
        __syncthreads();
        const int4* sh4 = (const int4*)sh;
        int n4 = npad >> 1;
        #pragma unroll 8
        for (int j = 0; j < n4; j++) {
            int4 q = sh4[j];                 // two (packed,idx) candidates
            unsigned ad;
            ad = __vabsdiffu4(tp, (unsigned)q.x);
            best = min(best, __dp4a(ad, ad, 0u) * 65536u + (unsigned)q.y);
            ad = __vabsdiffu4(tp, (unsigned)q.z);
            best = min(best, __dp4a(ad, ad, 0u) * 65536u + (unsigned)q.w);
        }
        __syncthreads();
    }
    if (active) atomicMin(&g_best[t.y], best);
}

// ------- kernel 3: gather rows (64B chunk/thread, MLP=4) + cursor reset -----
__global__ void k_gather(const float* __restrict__ feat, float* __restrict__ out,
                         int m) {
    int cid = blockIdx.x * blockDim.x + threadIdx.x;     // 64B chunk id
    int total = m * (CCH / 16);                          // 48 chunks per row
    if (cid < total) {
        int row = cid / (CCH / 16);
        int sub = cid - row * (CCH / 16);
        unsigned k = g_best[row];
        float4* o = (float4*)(out + (size_t)row * CCH) + sub * 4;
        if (k == 0xFFFFFFFFu) {                          // empty batch -> zeros
            float4 z = make_float4(0.f, 0.f, 0.f, 0.f);
            o[0] = z; o[1] = z; o[2] = z; o[3] = z;
        } else {
            const float4* f =
                (const float4*)(feat + (size_t)(k & 0xFFFFu) * CCH) + sub * 4;
            float4 v0 = f[0], v1 = f[1], v2 = f[2], v3 = f[3];
            o[0] = v0; o[1] = v1; o[2] = v2; o[3] = v3;
        }
    }
    // reset cursors for the NEXT replay (cursors unused by this kernel: no race)
    if (blockIdx.x == 0 && threadIdx.x < NB) {
        g_ccur[threadIdx.x] = 0;
        g_tcur[threadIdx.x] = 0;
    }
}

extern "C" void kernel_launch(void* const* d_in, const int* in_sizes, int n_in,
                              void* d_out, int out_size) {
    const float* feat    = (const float*)d_in[0];
    const int4*  coords  = (const int4*)d_in[1];
    const int4*  tcoords = (const int4*)d_in[2];
    float*       out     = (float*)d_out;

    int n = in_sizes[1] / 4;   // 50000
    int m = in_sizes[2] / 4;   // 8192

    k_scatter_all<<<(n + m + 255) / 256, 256>>>(coords, n, tcoords, m);

    int tiles = (m + TPB - 1) / TPB;           // worst case: all in one batch
    dim3 sgrid(tiles, SEGS, NB);
    k_search<<<sgrid, TPB>>>();

    int chunks = m * (CCH / 16);
    k_gather<<<(chunks + 255) / 256, 256>>>(feat, out, m);
}